// round 10
// baseline (speedup 1.0000x reference)
#include <cuda_runtime.h>
#include <cuda_bf16.h>
#include <cuda_fp16.h>
#include <cstdint>

#define N_NODES 50000
#define DEG     32
#define HEADS   4
#define OUT_F   16
#define IN_F    64
#define EDIM    (HEADS * OUT_F)   // 64 combined (h,o) features
#define PT_NODES 64               // nodes per proj block

typedef unsigned long long ull;

// Scratch: projected queries fp32 (256B/node); projected keys fp16 (128B/node,
// ONE cache line per neighbor row -> half the gather wavefronts & L2 traffic).
__device__ __align__(16) float  g_Qf[N_NODES * EDIM];
__device__ __align__(16) __half g_Kh[N_NODES * EDIM];

// ---------------------------------------------------------------------------
// helpers
// ---------------------------------------------------------------------------
__device__ __forceinline__ float ex2f(float x) {
    float r; asm("ex2.approx.ftz.f32 %0, %1;" : "=f"(r) : "f"(x)); return r;
}
__device__ __forceinline__ uint32_t pbf2(float x, float y) {
    __nv_bfloat162 h = __floats2bfloat162_rn(x, y);
    return *reinterpret_cast<uint32_t*>(&h);
}
__device__ __forceinline__ void mma_bf16(float* d, const uint32_t* a,
                                         uint32_t b0, uint32_t b1) {
    asm("mma.sync.aligned.m16n8k16.row.col.f32.bf16.bf16.f32 "
        "{%0,%1,%2,%3}, {%4,%5,%6,%7}, {%8,%9}, {%0,%1,%2,%3};"
        : "+f"(d[0]), "+f"(d[1]), "+f"(d[2]), "+f"(d[3])
        : "r"(a[0]), "r"(a[1]), "r"(a[2]), "r"(a[3]), "r"(b0), "r"(b1));
}

// ---------------------------------------------------------------------------
// Kernel 1: projection on TENSOR CORES (R9 design).
//   D[128 x 64nodes] = [qw ; kw] * Qtile[64 x 64nodes], split-bf16 3-term MMA.
// Epilogue: cols 0-63 -> g_Qf (fp32), cols 64-127 -> g_Kh (fp16).
// ---------------------------------------------------------------------------
#define BPITCH 72   // bf16 elems per B smem row
#define SPITCH 130  // floats per sS row

__global__ __launch_bounds__(256) void proj_kernel(
    const float* __restrict__ Q,      // [IN_F][N_NODES]
    const float* __restrict__ qw,     // [EDIM][IN_F]
    const float* __restrict__ kw)     // [EDIM][IN_F]
{
    __shared__ __nv_bfloat16 Bh[PT_NODES * BPITCH];  // 9.2 KB
    __shared__ __nv_bfloat16 Bl[PT_NODES * BPITCH];  // 9.2 KB
    __shared__ float         sS[PT_NODES * SPITCH];  // 33.3 KB

    const int tid  = threadIdx.x;
    const int warp = tid >> 5;
    const int lane = tid & 31;
    const int g    = lane >> 2;       // groupID
    const int t    = lane & 3;        // threadID in group
    const int n0   = blockIdx.x * PT_NODES;

    // ---- A fragments (weights), hi/lo split, straight from gmem ----
    const float* W = (warp < 4) ? qw : kw;
    const int er   = (warp & 3) * 16 + g;    // my e-row (and er+8)
    uint32_t ah[4][4], al[4][4];
#pragma unroll
    for (int kt = 0; kt < 4; kt++) {
        float2 p00 = *reinterpret_cast<const float2*>(&W[er * 64 + kt * 16 + 2 * t]);
        float2 p10 = *reinterpret_cast<const float2*>(&W[(er + 8) * 64 + kt * 16 + 2 * t]);
        float2 p01 = *reinterpret_cast<const float2*>(&W[er * 64 + kt * 16 + 8 + 2 * t]);
        float2 p11 = *reinterpret_cast<const float2*>(&W[(er + 8) * 64 + kt * 16 + 8 + 2 * t]);
#define SPLIT(reg_h, reg_l, v)                                              \
        {                                                                   \
            float hx, hy;                                                   \
            hx = __bfloat162float(__float2bfloat16_rn((v).x));              \
            hy = __bfloat162float(__float2bfloat16_rn((v).y));              \
            reg_h = pbf2(hx, hy);                                           \
            reg_l = pbf2((v).x - hx, (v).y - hy);                           \
        }
        SPLIT(ah[kt][0], al[kt][0], p00);
        SPLIT(ah[kt][1], al[kt][1], p10);
        SPLIT(ah[kt][2], al[kt][2], p01);
        SPLIT(ah[kt][3], al[kt][3], p11);
    }

    // ---- Q tile: fp32 -> (hi, lo) bf16 pairs in smem ----
    uint32_t* Bh32 = reinterpret_cast<uint32_t*>(Bh);
    uint32_t* Bl32 = reinterpret_cast<uint32_t*>(Bl);
#pragma unroll
    for (int r = 0; r < 8; r++) {
        int e2 = tid + 256 * r;                 // 2048 pairs
        int n  = e2 & 63;
        int p  = e2 >> 6;                       // 0..31
        int nn = min(n0 + n, N_NODES - 1);
        float x0 = Q[(2 * p + 0) * N_NODES + nn];
        float x1 = Q[(2 * p + 1) * N_NODES + nn];
        float h0 = __bfloat162float(__float2bfloat16_rn(x0));
        float h1 = __bfloat162float(__float2bfloat16_rn(x1));
        Bh32[n * (BPITCH / 2) + p] = pbf2(h0, h1);
        Bl32[n * (BPITCH / 2) + p] = pbf2(x0 - h0, x1 - h1);
    }
    __syncthreads();

    // ---- MMA mainloop: 8 n-tiles x 4 k-tiles x 3 terms ----
#pragma unroll
    for (int nt = 0; nt < 8; nt++) {
        float d[4] = {0.f, 0.f, 0.f, 0.f};
#pragma unroll
        for (int kt = 0; kt < 4; kt++) {
            int boff = (nt * 8 + g) * BPITCH + kt * 16 + 2 * t;
            uint32_t bh0 = *reinterpret_cast<const uint32_t*>(&Bh[boff]);
            uint32_t bh1 = *reinterpret_cast<const uint32_t*>(&Bh[boff + 8]);
            uint32_t bl0 = *reinterpret_cast<const uint32_t*>(&Bl[boff]);
            uint32_t bl1 = *reinterpret_cast<const uint32_t*>(&Bl[boff + 8]);
            mma_bf16(d, ah[kt], bh0, bh1);   // hi*hi
            mma_bf16(d, al[kt], bh0, bh1);   // lo*hi
            mma_bf16(d, ah[kt], bl0, bl1);   // hi*lo
        }
        int col0 = er + ((warp >= 4) ? 64 : 0);
        int nl   = nt * 8 + 2 * t;
        sS[nl * SPITCH + col0]           = d[0];
        sS[(nl + 1) * SPITCH + col0]     = d[1];
        sS[nl * SPITCH + col0 + 8]       = d[2];
        sS[(nl + 1) * SPITCH + col0 + 8] = d[3];
    }
    __syncthreads();

    // ---- coalesced store: cols 0-63 -> g_Qf fp32, 64-127 -> g_Kh fp16 ----
    const int nmax = min(PT_NODES, N_NODES - n0);
    for (int idx = tid; idx < nmax * 128; idx += 256) {
        int n = idx >> 7, c = idx & 127;
        float v = sS[n * SPITCH + c];
        if (c < 64) g_Qf[(n0 + n) * EDIM + c]        = v;
        else        g_Kh[(n0 + n) * EDIM + (c - 64)] = __float2half_rn(v);
    }
}

// ---------------------------------------------------------------------------
// Kernel 2: gather + attention + aggregate. R8/R9 structure, fp16 K-table:
// warp per node, half = lane>>4 handles neighbor 2t+half, lane owns 4
// features (8 bytes fp16) at foff=(lane&15)*4 -> each half-warp LDG.64 covers
// a neighbor row's SINGLE 128B line. Hoisted indices + unconditional clamped
// loads; fp32 math after convert; max-free softmax in exp2 domain; lrelu
// folded into the dot via |x|.
// ---------------------------------------------------------------------------
__global__ __launch_bounds__(256) void gat_kernel(
    const int*   __restrict__ adj,    // [N_NODES][DEG]
    const float* __restrict__ aw,     // [EDIM]
    float*       __restrict__ out)    // [EDIM][N_NODES]
{
    const unsigned FULL = 0xffffffffu;
    const float LOG2E = 1.4426950408889634f;
    const int warp = threadIdx.x >> 5;
    const int lane = threadIdx.x & 31;
    const int half = lane >> 4;
    const int foff = (lane & 15) * 4;
    const int n = blockIdx.x * 8 + warp;          // grid exact: 6250*8 = 50000

    __shared__ float sOut[EDIM][9];               // pitch 9 to spread banks

    int j = adj[n * DEG + lane];
    int jks[DEG / 2];
#pragma unroll
    for (int t = 0; t < DEG / 2; t++)
        jks[t] = __shfl_sync(FULL, j, (t << 1) | half);

    float4 qf = *reinterpret_cast<const float4*>(&g_Qf[n * EDIM + foff]);
    float4 w4 = *reinterpret_cast<const float4*>(&aw[foff]);
    // lrelu(x) = 0.505x + 0.495|x| (slope 0.01); fold log2(e) for exp2 domain
    const float c1 = 0.505f * LOG2E, c2 = 0.495f * LOG2E;
    float w1x = w4.x * c1, w1y = w4.y * c1, w1z = w4.z * c1, w1w = w4.w * c1;
    float w2x = w4.x * c2, w2y = w4.y * c2, w2z = w4.z * c2, w2w = w4.w * c2;

    float s = 0.f;
    float4 acc = make_float4(0.f, 0.f, 0.f, 0.f);

#pragma unroll
    for (int t = 0; t < DEG / 2; t++) {
        int jk  = jks[t];
        int row = max(jk, 0);                     // clamp: load unconditionally
        uint2 kpu = *reinterpret_cast<const uint2*>(&g_Kh[row * EDIM + foff]);
        float2 k01 = __half22float2(*reinterpret_cast<__half2*>(&kpu.x));
        float2 k23 = __half22float2(*reinterpret_cast<__half2*>(&kpu.y));

        // x = q + k, dot with split weights (|x| folds into FFMA src modifier)
        float x0 = qf.x + k01.x, x1 = qf.y + k01.y;
        float x2 = qf.z + k23.x, x3 = qf.w + k23.y;
        float p1, p2;
        p1 = w1x * x0;            p2 = w2x * fabsf(x0);
        p1 = fmaf(w1y, x1, p1);   p2 = fmaf(w2y, fabsf(x1), p2);
        p1 = fmaf(w1z, x2, p1);   p2 = fmaf(w2z, fabsf(x2), p2);
        p1 = fmaf(w1w, x3, p1);   p2 = fmaf(w2w, fabsf(x3), p2);
        float p = p1 + p2;

        // reduce over 16 out-features of this head (4 lanes x 4 feats)
        p += __shfl_xor_sync(FULL, p, 1);
        p += __shfl_xor_sync(FULL, p, 2);

        // max-free softmax term; padded edge -> weight 0 (kills garbage kf)
        float e = (jk >= 0) ? ex2f(p) : 0.f;
        s += e;
        acc.x = fmaf(e, k01.x, acc.x);
        acc.y = fmaf(e, k01.y, acc.y);
        acc.z = fmaf(e, k23.x, acc.z);
        acc.w = fmaf(e, k23.y, acc.w);
    }

    // merge the two halves (even/odd neighbors); same features at lane^16
    s     += __shfl_xor_sync(FULL, s, 16);
    acc.x += __shfl_xor_sync(FULL, acc.x, 16);
    acc.y += __shfl_xor_sync(FULL, acc.y, 16);
    acc.z += __shfl_xor_sync(FULL, acc.z, 16);
    acc.w += __shfl_xor_sync(FULL, acc.w, 16);

    // all-pad rows: s == 0, acc == 0 -> output exactly 0 (matches reference)
    float inv = __frcp_rn(fmaxf(s, 1e-30f));
    if (half == 0) {
        sOut[foff + 0][warp] = acc.x * inv;
        sOut[foff + 1][warp] = acc.y * inv;
        sOut[foff + 2][warp] = acc.z * inv;
        sOut[foff + 3][warp] = acc.w * inv;
    }
    __syncthreads();

    // Coalesced store: 512 elements, 8 consecutive n per feature row.
    const int n0 = blockIdx.x * 8;
#pragma unroll
    for (int idx = threadIdx.x; idx < EDIM * 8; idx += 256) {
        int e  = idx >> 3;
        int nn = idx & 7;
        out[e * N_NODES + n0 + nn] = sOut[e][nn];
    }
}

// ---------------------------------------------------------------------------
extern "C" void kernel_launch(void* const* d_in, const int* in_sizes, int n_in,
                              void* d_out, int out_size)
{
    const int*   adj = (const int*)  d_in[0];   // [50000*32] int32
    const float* Q   = (const float*)d_in[1];   // [64*50000]
    const float* qw  = (const float*)d_in[2];   // [4*16*64]
    const float* kw  = (const float*)d_in[3];   // [4*16*64]
    const float* aw  = (const float*)d_in[4];   // [4*16]
    float* out = (float*)d_out;                 // [4*16*50000]

    (void)in_sizes; (void)n_in; (void)out_size;

    proj_kernel<<<(N_NODES + PT_NODES - 1) / PT_NODES, 256>>>(Q, qw, kw);
    gat_kernel<<<N_NODES / 8, 256>>>(adj, aw, out);
}

// round 11
// speedup vs baseline: 1.1232x; 1.1232x over previous
#include <cuda_runtime.h>
#include <cuda_bf16.h>
#include <cuda_fp16.h>
#include <cstdint>

#define N_NODES 50000
#define DEG     32
#define HEADS   4
#define OUT_F   16
#define IN_F    64
#define EDIM    (HEADS * OUT_F)   // 64 combined (h,o) features
#define PT_NODES 64               // nodes per proj block

typedef unsigned long long ull;

// Scratch: projected queries fp32 (256B/node); projected keys fp16 (128B/node,
// ONE cache line per neighbor row).
__device__ __align__(16) float  g_Qf[N_NODES * EDIM];
__device__ __align__(16) __half g_Kh[N_NODES * EDIM];

// ---------------------------------------------------------------------------
// helpers
// ---------------------------------------------------------------------------
__device__ __forceinline__ ull pack2(float a, float b) {
    ull r; asm("mov.b64 %0, {%1, %2};" : "=l"(r) : "f"(a), "f"(b)); return r;
}
__device__ __forceinline__ float2 unpack2(ull v) {
    float2 r; asm("mov.b64 {%0, %1}, %2;" : "=f"(r.x), "=f"(r.y) : "l"(v)); return r;
}
__device__ __forceinline__ void fma2(ull& d, ull a, ull b) {
    asm("fma.rn.f32x2 %0, %1, %2, %0;" : "+l"(d) : "l"(a), "l"(b));
}
__device__ __forceinline__ float ex2f(float x) {
    float r; asm("ex2.approx.ftz.f32 %0, %1;" : "=f"(r) : "f"(x)); return r;
}
__device__ __forceinline__ uint32_t pbf2(float x, float y) {
    __nv_bfloat162 h = __floats2bfloat162_rn(x, y);
    return *reinterpret_cast<uint32_t*>(&h);
}
__device__ __forceinline__ void mma_bf16(float* d, const uint32_t* a,
                                         uint32_t b0, uint32_t b1) {
    asm("mma.sync.aligned.m16n8k16.row.col.f32.bf16.bf16.f32 "
        "{%0,%1,%2,%3}, {%4,%5,%6,%7}, {%8,%9}, {%0,%1,%2,%3};"
        : "+f"(d[0]), "+f"(d[1]), "+f"(d[2]), "+f"(d[3])
        : "r"(a[0]), "r"(a[1]), "r"(a[2]), "r"(a[3]), "r"(b0), "r"(b1));
}

// ---------------------------------------------------------------------------
// Kernel 1: projection on TENSOR CORES (unchanged, R9/R10 design).
//   D[128 x 64nodes] = [qw ; kw] * Qtile[64 x 64nodes], split-bf16 3-term MMA.
// Epilogue: cols 0-63 -> g_Qf (fp32), cols 64-127 -> g_Kh (fp16).
// ---------------------------------------------------------------------------
#define BPITCH 72   // bf16 elems per B smem row
#define SPITCH 130  // floats per sS row

__global__ __launch_bounds__(256) void proj_kernel(
    const float* __restrict__ Q,      // [IN_F][N_NODES]
    const float* __restrict__ qw,     // [EDIM][IN_F]
    const float* __restrict__ kw)     // [EDIM][IN_F]
{
    __shared__ __nv_bfloat16 Bh[PT_NODES * BPITCH];  // 9.2 KB
    __shared__ __nv_bfloat16 Bl[PT_NODES * BPITCH];  // 9.2 KB
    __shared__ float         sS[PT_NODES * SPITCH];  // 33.3 KB

    const int tid  = threadIdx.x;
    const int warp = tid >> 5;
    const int lane = tid & 31;
    const int g    = lane >> 2;       // groupID
    const int t    = lane & 3;        // threadID in group
    const int n0   = blockIdx.x * PT_NODES;

    // ---- A fragments (weights), hi/lo split, straight from gmem ----
    const float* W = (warp < 4) ? qw : kw;
    const int er   = (warp & 3) * 16 + g;    // my e-row (and er+8)
    uint32_t ah[4][4], al[4][4];
#pragma unroll
    for (int kt = 0; kt < 4; kt++) {
        float2 p00 = *reinterpret_cast<const float2*>(&W[er * 64 + kt * 16 + 2 * t]);
        float2 p10 = *reinterpret_cast<const float2*>(&W[(er + 8) * 64 + kt * 16 + 2 * t]);
        float2 p01 = *reinterpret_cast<const float2*>(&W[er * 64 + kt * 16 + 8 + 2 * t]);
        float2 p11 = *reinterpret_cast<const float2*>(&W[(er + 8) * 64 + kt * 16 + 8 + 2 * t]);
#define SPLIT(reg_h, reg_l, v)                                              \
        {                                                                   \
            float hx, hy;                                                   \
            hx = __bfloat162float(__float2bfloat16_rn((v).x));              \
            hy = __bfloat162float(__float2bfloat16_rn((v).y));              \
            reg_h = pbf2(hx, hy);                                           \
            reg_l = pbf2((v).x - hx, (v).y - hy);                           \
        }
        SPLIT(ah[kt][0], al[kt][0], p00);
        SPLIT(ah[kt][1], al[kt][1], p10);
        SPLIT(ah[kt][2], al[kt][2], p01);
        SPLIT(ah[kt][3], al[kt][3], p11);
    }

    // ---- Q tile: fp32 -> (hi, lo) bf16 pairs in smem ----
    uint32_t* Bh32 = reinterpret_cast<uint32_t*>(Bh);
    uint32_t* Bl32 = reinterpret_cast<uint32_t*>(Bl);
#pragma unroll
    for (int r = 0; r < 8; r++) {
        int e2 = tid + 256 * r;                 // 2048 pairs
        int n  = e2 & 63;
        int p  = e2 >> 6;                       // 0..31
        int nn = min(n0 + n, N_NODES - 1);
        float x0 = Q[(2 * p + 0) * N_NODES + nn];
        float x1 = Q[(2 * p + 1) * N_NODES + nn];
        float h0 = __bfloat162float(__float2bfloat16_rn(x0));
        float h1 = __bfloat162float(__float2bfloat16_rn(x1));
        Bh32[n * (BPITCH / 2) + p] = pbf2(h0, h1);
        Bl32[n * (BPITCH / 2) + p] = pbf2(x0 - h0, x1 - h1);
    }
    __syncthreads();

    // ---- MMA mainloop: 8 n-tiles x 4 k-tiles x 3 terms ----
#pragma unroll
    for (int nt = 0; nt < 8; nt++) {
        float d[4] = {0.f, 0.f, 0.f, 0.f};
#pragma unroll
        for (int kt = 0; kt < 4; kt++) {
            int boff = (nt * 8 + g) * BPITCH + kt * 16 + 2 * t;
            uint32_t bh0 = *reinterpret_cast<const uint32_t*>(&Bh[boff]);
            uint32_t bh1 = *reinterpret_cast<const uint32_t*>(&Bh[boff + 8]);
            uint32_t bl0 = *reinterpret_cast<const uint32_t*>(&Bl[boff]);
            uint32_t bl1 = *reinterpret_cast<const uint32_t*>(&Bl[boff + 8]);
            mma_bf16(d, ah[kt], bh0, bh1);   // hi*hi
            mma_bf16(d, al[kt], bh0, bh1);   // lo*hi
            mma_bf16(d, ah[kt], bl0, bl1);   // hi*lo
        }
        int col0 = er + ((warp >= 4) ? 64 : 0);
        int nl   = nt * 8 + 2 * t;
        sS[nl * SPITCH + col0]           = d[0];
        sS[(nl + 1) * SPITCH + col0]     = d[1];
        sS[nl * SPITCH + col0 + 8]       = d[2];
        sS[(nl + 1) * SPITCH + col0 + 8] = d[3];
    }
    __syncthreads();

    // ---- coalesced store: cols 0-63 -> g_Qf fp32, 64-127 -> g_Kh fp16 ----
    const int nmax = min(PT_NODES, N_NODES - n0);
    for (int idx = tid; idx < nmax * 128; idx += 256) {
        int n = idx >> 7, c = idx & 127;
        float v = sS[n * SPITCH + c];
        if (c < 64) g_Qf[(n0 + n) * EDIM + c]        = v;
        else        g_Kh[(n0 + n) * EDIM + (c - 64)] = __float2half_rn(v);
    }
}

// ---------------------------------------------------------------------------
// Kernel 2: gather + attention + aggregate. 4 neighbors/iter on fp16 rows:
// group g = lane>>3 handles neighbor 4t+g; lane wl = lane&7 owns features
// [8wl, 8wl+8) -> one LDG.128 covers a neighbor's ENTIRE 128B row (1 line).
// Head = wl>>1 (16 feats on a lane pair) -> single xor-1 logit reduction.
// lrelu via p = C1*(w.x) + C2*(w.|x|) (abs folds into FFMA, single w array).
// Max-free softmax in exp2 domain; hoisted indices, unconditional clamped
// loads; packed f32x2 aggregation. Merge 4 groups via xor-8/xor-16.
// Block = 128 thr = 4 nodes (finer SM packing under ~55 regs).
// ---------------------------------------------------------------------------
__global__ __launch_bounds__(128) void gat_kernel(
    const int*   __restrict__ adj,    // [N_NODES][DEG]
    const float* __restrict__ aw,     // [EDIM]
    float*       __restrict__ out)    // [EDIM][N_NODES]
{
    const unsigned FULL = 0xffffffffu;
    const float LOG2E = 1.4426950408889634f;
    const float C1 = 0.505f * LOG2E, C2 = 0.495f * LOG2E;
    const int warp = threadIdx.x >> 5;
    const int lane = threadIdx.x & 31;
    const int g    = lane >> 3;
    const int wl   = lane & 7;
    const int n = blockIdx.x * 4 + warp;          // grid exact: 12500*4 = 50000

    __shared__ float sOut[EDIM][5];               // pitch 5 (4 warps)

    int j = adj[n * DEG + lane];
    int jks[DEG / 4];
#pragma unroll
    for (int t = 0; t < DEG / 4; t++)
        jks[t] = __shfl_sync(FULL, j, (t << 2) | g);

    // my 8 q features and 8 attention weights (true order, contiguous)
    float4 qa = *reinterpret_cast<const float4*>(&g_Qf[n * EDIM + 8 * wl]);
    float4 qb = *reinterpret_cast<const float4*>(&g_Qf[n * EDIM + 8 * wl + 4]);
    float4 wa = *reinterpret_cast<const float4*>(&aw[8 * wl]);
    float4 wb = *reinterpret_cast<const float4*>(&aw[8 * wl + 4]);

    float s = 0.f;
    ull acc01 = 0ull, acc23 = 0ull, acc45 = 0ull, acc67 = 0ull;

#pragma unroll
    for (int t = 0; t < DEG / 4; t++) {
        int jk  = jks[t];
        int row = max(jk, 0);                     // clamp: load unconditionally
        uint4 kv = *reinterpret_cast<const uint4*>(&g_Kh[row * EDIM + 8 * wl]);
        float2 k01 = __half22float2(*reinterpret_cast<__half2*>(&kv.x));
        float2 k23 = __half22float2(*reinterpret_cast<__half2*>(&kv.y));
        float2 k45 = __half22float2(*reinterpret_cast<__half2*>(&kv.z));
        float2 k67 = __half22float2(*reinterpret_cast<__half2*>(&kv.w));

        // x = q + k; sx = w.x, sa = w.|x| (|x| folds into FFMA src modifier)
        float x0 = qa.x + k01.x, x1 = qa.y + k01.y;
        float x2 = qa.z + k23.x, x3 = qa.w + k23.y;
        float x4 = qb.x + k45.x, x5 = qb.y + k45.y;
        float x6 = qb.z + k67.x, x7 = qb.w + k67.y;
        float sx, sa;
        sx = wa.x * x0;           sa = wa.x * fabsf(x0);
        sx = fmaf(wa.y, x1, sx);  sa = fmaf(wa.y, fabsf(x1), sa);
        sx = fmaf(wa.z, x2, sx);  sa = fmaf(wa.z, fabsf(x2), sa);
        sx = fmaf(wa.w, x3, sx);  sa = fmaf(wa.w, fabsf(x3), sa);
        sx = fmaf(wb.x, x4, sx);  sa = fmaf(wb.x, fabsf(x4), sa);
        sx = fmaf(wb.y, x5, sx);  sa = fmaf(wb.y, fabsf(x5), sa);
        sx = fmaf(wb.z, x6, sx);  sa = fmaf(wb.z, fabsf(x6), sa);
        sx = fmaf(wb.w, x7, sx);  sa = fmaf(wb.w, fabsf(x7), sa);
        float p = fmaf(C1, sx, C2 * sa);          // log2-domain logit (8 feats)

        // 16 feats of my head live on lane pair (wl^1): single xor-1 shuffle
        p += __shfl_xor_sync(FULL, p, 1);

        // max-free softmax term; padded edge -> weight 0 (kills garbage kf)
        float e = (jk >= 0) ? ex2f(p) : 0.f;
        s += e;
        ull e2 = pack2(e, e);
        fma2(acc01, e2, pack2(k01.x, k01.y));
        fma2(acc23, e2, pack2(k23.x, k23.y));
        fma2(acc45, e2, pack2(k45.x, k45.y));
        fma2(acc67, e2, pack2(k67.x, k67.y));
    }

    // merge the 4 neighbor-groups (same wl across g): xor 8, then xor 16
    float2 A = unpack2(acc01), B = unpack2(acc23);
    float2 C = unpack2(acc45), D = unpack2(acc67);
#pragma unroll
    for (int d = 8; d <= 16; d <<= 1) {
        s   += __shfl_xor_sync(FULL, s, d);
        A.x += __shfl_xor_sync(FULL, A.x, d);
        A.y += __shfl_xor_sync(FULL, A.y, d);
        B.x += __shfl_xor_sync(FULL, B.x, d);
        B.y += __shfl_xor_sync(FULL, B.y, d);
        C.x += __shfl_xor_sync(FULL, C.x, d);
        C.y += __shfl_xor_sync(FULL, C.y, d);
        D.x += __shfl_xor_sync(FULL, D.x, d);
        D.y += __shfl_xor_sync(FULL, D.y, d);
    }

    // all-pad rows: s == 0, acc == 0 -> output exactly 0 (matches reference)
    float inv = __frcp_rn(fmaxf(s, 1e-30f));
    if (g == 0) {
        sOut[8 * wl + 0][warp] = A.x * inv;
        sOut[8 * wl + 1][warp] = A.y * inv;
        sOut[8 * wl + 2][warp] = B.x * inv;
        sOut[8 * wl + 3][warp] = B.y * inv;
        sOut[8 * wl + 4][warp] = C.x * inv;
        sOut[8 * wl + 5][warp] = C.y * inv;
        sOut[8 * wl + 6][warp] = D.x * inv;
        sOut[8 * wl + 7][warp] = D.y * inv;
    }
    __syncthreads();

    // Coalesced store: 256 elements, 4 consecutive n per feature row.
    const int n0 = blockIdx.x * 4;
#pragma unroll
    for (int idx = threadIdx.x; idx < EDIM * 4; idx += 128) {
        int e  = idx >> 2;
        int nn = idx & 3;
        out[e * N_NODES + n0 + nn] = sOut[e][nn];
    }
}

// ---------------------------------------------------------------------------
extern "C" void kernel_launch(void* const* d_in, const int* in_sizes, int n_in,
                              void* d_out, int out_size)
{
    const int*   adj = (const int*)  d_in[0];   // [50000*32] int32
    const float* Q   = (const float*)d_in[1];   // [64*50000]
    const float* qw  = (const float*)d_in[2];   // [4*16*64]
    const float* kw  = (const float*)d_in[3];   // [4*16*64]
    const float* aw  = (const float*)d_in[4];   // [4*16]
    float* out = (float*)d_out;                 // [4*16*50000]

    (void)in_sizes; (void)n_in; (void)out_size;

    proj_kernel<<<(N_NODES + PT_NODES - 1) / PT_NODES, 256>>>(Q, qw, kw);
    gat_kernel<<<N_NODES / 4, 128>>>(adj, aw, out);
}